// round 14
// baseline (speedup 1.0000x reference)
#include <cuda_runtime.h>

// Problem constants (fixed: B=16, N=8192, C=256, num_points=2048)
#define BB   16
#define NN   8192
#define CC   256
#define MM   2048
#define TT   1024          // threads per FPS block
#define PPT  (NN / TT)     // points per thread = 8
#define NPAIR (PPT / 2)    // f32x2 pairs per thread = 4

// Scratch: selected indices, written by FPS kernel, read by gather kernel.
__device__ int g_idx[BB * MM];

// Dynamic smem: sq4[NN] float4 | pvi[64] uint2 | initv[32] | initi[32] |
//               cent[96] | wext4[32] float4 | skx[NN] | ski[NN]
#define SMEM_BYTES (NN * 16 + 64 * 8 + 32 * 4 + 32 * 4 + 96 * 4 + 32 * 16 \
                    + NN * 4 + NN * 4)

// ---- packed f32x2 helpers (sm_103a) ---------------------------------------
__device__ __forceinline__ unsigned long long pack2(float lo, float hi) {
    unsigned long long r;
    asm("mov.b64 %0, {%1, %2};" : "=l"(r) : "f"(lo), "f"(hi));
    return r;
}
__device__ __forceinline__ void unpack2(unsigned long long v, float& lo, float& hi) {
    asm("mov.b64 {%0, %1}, %2;" : "=f"(lo), "=f"(hi) : "l"(v));
}
__device__ __forceinline__ unsigned long long add2(unsigned long long a, unsigned long long b) {
    unsigned long long r;
    asm("add.rn.f32x2 %0, %1, %2;" : "=l"(r) : "l"(a), "l"(b));
    return r;
}
__device__ __forceinline__ unsigned long long mul2(unsigned long long a, unsigned long long b) {
    unsigned long long r;
    asm("mul.rn.f32x2 %0, %1, %2;" : "=l"(r) : "l"(a), "l"(b));
    return r;
}
// ---------------------------------------------------------------------------

__device__ __forceinline__ float warp_sum(float x) {
    #pragma unroll
    for (int o = 16; o > 0; o >>= 1)
        x += __shfl_xor_sync(0xFFFFFFFFu, x, o);
    return x;
}
__device__ __forceinline__ float warp_min(float x) {
    #pragma unroll
    for (int o = 16; o > 0; o >>= 1)
        x = fminf(x, __shfl_xor_sync(0xFFFFFFFFu, x, o));
    return x;
}
__device__ __forceinline__ float warp_max(float x) {
    #pragma unroll
    for (int o = 16; o > 0; o >>= 1)
        x = fmaxf(x, __shfl_xor_sync(0xFFFFFFFFu, x, o));
    return x;
}

extern "C" __global__ void __launch_bounds__(TT, 1)
fps_kernel(const float* __restrict__ pts,   // [B, 3, N]
           float* __restrict__ out_pts)     // [B, M, 3]
{
    extern __shared__ unsigned char smraw[];
    float4*   sq4   = (float4*)smraw;                  // [NN] orig-indexed coords
    uint2*    pvi   = (uint2*)(smraw + NN * 16);       // [64] (val,cand), 2 bufs
    unsigned* initv = (unsigned*)(pvi + 64);           // [32]
    unsigned* initi = initv + 32;                      // [32]
    float*    cent  = (float*)(initi + 32);            // [96]
    float4*   wext4 = (float4*)(cent + 96);            // [32] (xmn,xmx,ymn,ymx)
    float*    skx   = (float*)(wext4 + 32);            // [NN] sort keys
    int*      ski   = (int*)(skx + NN);                // [NN] orig indices
    unsigned* sku   = (unsigned*)skx;                  // uint view for pass 2

    const int b    = blockIdx.x;
    const int tid  = threadIdx.x;
    const int lane = tid & 31;
    const int warp = tid >> 5;

    const float* px = pts + (size_t)b * 3 * NN;
    const float* py = px + NN;
    const float* pz = px + 2 * NN;

    // ---- load (orig layout), centroid sums, x-sort-key init ----
    float s1 = 0.f, s2 = 0.f, s3 = 0.f;
    #pragma unroll
    for (int k = 0; k < PPT; k++) {
        int n = tid + k * TT;               // coalesced
        float x = px[n], y = py[n], z = pz[n];
        sq4[n] = make_float4(x, y, z, 0.f);
        skx[n] = x; ski[n] = n;
        s1 += x; s2 += y; s3 += z;
    }

    // Deterministic centroid (exact, one-shot).
    s1 = warp_sum(s1); s2 = warp_sum(s2); s3 = warp_sum(s3);
    if (lane == 0) { cent[warp] = s1; cent[32 + warp] = s2; cent[64 + warp] = s3; }

    // ---- pass 1: bitonic sort by x (permutation-preserving; sort quality
    //      only affects pruning, never correctness) ----
    for (int k = 2; k <= NN; k <<= 1) {
        for (int j = k >> 1; j > 0; j >>= 1) {
            __syncthreads();
            #pragma unroll 4
            for (int t = tid; t < NN / 2; t += TT) {
                int i = 2 * t - (t & (j - 1));
                int l = i + j;
                bool up = ((i & k) == 0);
                float a = skx[i], c = skx[l];
                bool sw = up ? (a > c) : (a < c);
                if (sw) {
                    skx[i] = c; skx[l] = a;
                    int ta = ski[i]; ski[i] = ski[l]; ski[l] = ta;
                }
            }
        }
    }
    __syncthreads();

    // ---- pass 2 keys: (xbin from x-rank, sortable y). 8 equal-count x-bins;
    //      within a bin, order by y -> warps own 2-D-compact tiles. ----
    #pragma unroll
    for (int k = 0; k < PPT; k++) {
        int r = tid + k * TT;
        int idx = ski[r];
        unsigned ub = __float_as_uint(sq4[idx].y);
        ub = (ub & 0x80000000u) ? ~ub : (ub | 0x80000000u);   // sortable float
        sku[r] = ((unsigned)(r >> 10) << 29) | (ub >> 3);
    }
    // ---- pass 2: bitonic sort by composite uint key ----
    for (int k = 2; k <= NN; k <<= 1) {
        for (int j = k >> 1; j > 0; j >>= 1) {
            __syncthreads();
            #pragma unroll 4
            for (int t = tid; t < NN / 2; t += TT) {
                int i = 2 * t - (t & (j - 1));
                int l = i + j;
                bool up = ((i & k) == 0);
                unsigned a = sku[i], c = sku[l];
                bool sw = up ? (a > c) : (a < c);
                if (sw) {
                    sku[i] = c; sku[l] = a;
                    int ta = ski[i]; ski[i] = ski[l]; ski[l] = ta;
                }
            }
        }
    }
    __syncthreads();

    // ---- reorder into registers: warp w owns tile ranks [256w, 256w+256) ----
    unsigned long long X2[NPAIR], Y2[NPAIR], Z2[NPAIR];
    unsigned OI2[NPAIR];                    // packed orig indices (lo | hi<<16)
    float dr[PPT];
    {
        float xs[PPT], ys[PPT], zs[PPT];
        unsigned oi[PPT];
        const int base = warp * 256 + lane;
        #pragma unroll
        for (int k = 0; k < PPT; k++) {
            int r = base + 32 * k;
            int idx = ski[r];
            float4 p = sq4[idx];
            xs[k] = p.x; ys[k] = p.y; zs[k] = p.z;
            oi[k] = (unsigned)idx;
            dr[k] = 1e10f;
        }
        #pragma unroll
        for (int j = 0; j < NPAIR; j++) {
            X2[j] = pack2(xs[2 * j], xs[2 * j + 1]);
            Y2[j] = pack2(ys[2 * j], ys[2 * j + 1]);
            Z2[j] = pack2(zs[2 * j], zs[2 * j + 1]);
            OI2[j] = oi[2 * j] | (oi[2 * j + 1] << 16);
        }
        // Warp 2-D bbox (from held points -> always safe) -> smem.
        float xmn = xs[0], xmx = xs[0], ymn = ys[0], ymx = ys[0];
        #pragma unroll
        for (int k = 1; k < PPT; k++) {
            xmn = fminf(xmn, xs[k]); xmx = fmaxf(xmx, xs[k]);
            ymn = fminf(ymn, ys[k]); ymx = fmaxf(ymx, ys[k]);
        }
        xmn = warp_min(xmn); xmx = warp_max(xmx);
        ymn = warp_min(ymn); ymx = warp_max(ymx);
        if (lane == 0) wext4[warp] = make_float4(xmn, xmx, ymn, ymx);

        // Centroid finalize.
        float cx = warp_sum(cent[lane])      * (1.0f / NN);
        float cy = warp_sum(cent[32 + lane]) * (1.0f / NN);
        float cz = warp_sum(cent[64 + lane]) * (1.0f / NN);

        // d0 = ||p - centroid||^2, initial farthest (exact plain form;
        // orig-idx tie-break since held points are no longer index-ordered).
        float best = -1.0f; unsigned bi = 0xFFFFFFFFu;
        #pragma unroll
        for (int k = 0; k < PPT; k++) {
            float dx = xs[k] - cx, dy = ys[k] - cy, dz = zs[k] - cz;
            float d = __fadd_rn(__fadd_rn(__fmul_rn(dx, dx), __fmul_rn(dy, dy)),
                                __fmul_rn(dz, dz));
            if (d > best)            { best = d; bi = oi[k]; }
            else if (d == best && oi[k] < bi) bi = oi[k];
        }
        unsigned vb = __float_as_uint(best);
        unsigned m1 = __reduce_max_sync(0xFFFFFFFFu, vb);
        unsigned c1 = (vb == m1) ? bi : 0xFFFFFFFFu;
        unsigned i1 = __reduce_min_sync(0xFFFFFFFFu, c1);
        if (lane == 0) { initv[warp] = m1; initi[warp] = i1; }
    }
    __syncthreads();
    unsigned far;
    {
        unsigned v2 = initv[lane];
        unsigned i2 = initi[lane];
        unsigned m2 = __reduce_max_sync(0xFFFFFFFFu, v2);
        unsigned c2 = (v2 == m2) ? i2 : 0xFFFFFFFFu;
        far = __reduce_min_sync(0xFFFFFFFFu, c2);
    }

    float* outp = out_pts + (size_t)b * MM * 3;
    int*   idxp = g_idx + b * MM;

    // Per-warp cached state (exact while skipped): max-dr bits, min orig idx
    // among bit-equal ties, and prune threshold bndf = wvb * 1.00001.
    // Huge initial bndf -> first iteration always updates, initializing all.
    unsigned wvb   = __float_as_uint(1e10f);
    unsigned wcand = 0xFFFFFFFFu;
    float bndf = 1e30f;

    for (int m = 0; m < MM; m++) {
        const int buf = m & 1;
        // Broadcast the selected point (one LDS.128, orig-indexed table).
        float4 q = sq4[far];
        if (tid == 0) {
            idxp[m] = (int)far;
            outp[m * 3 + 0] = q.x;
            outp[m * 3 + 1] = q.y;
            outp[m * 3 + 2] = q.z;
        }

        // 2-D bbox prune: skip iff gx^2+gy^2 >= wvb*1.00001. Then for every
        // held point d_computed >= d_exact*(1-3e-7) >= gap2_exact
        // >= gap2_comp*(1-5ulp) > wvb >= all dr_k  ==> every fminf below is a
        // bit-level no-op; dr, wvb, wcand keep their exact values.
        float4 e = wext4[warp];                          // warp-uniform LDS.128
        float gx = fmaxf(fmaxf(e.x - q.x, q.x - e.y), 0.0f);
        float gy = fmaxf(fmaxf(e.z - q.y, q.y - e.w), 0.0f);
        float g2 = __fmaf_rn(gy, gy, __fmul_rn(gx, gx));
        if (g2 < bndf) {
            // Exact update (reference-rounded, no contraction).
            unsigned long long nqx2 = pack2(-q.x, -q.x);
            unsigned long long nqy2 = pack2(-q.y, -q.y);
            unsigned long long nqz2 = pack2(-q.z, -q.z);
            #pragma unroll
            for (int j = 0; j < NPAIR; j++) {
                unsigned long long dx2 = add2(X2[j], nqx2);
                unsigned long long dy2 = add2(Y2[j], nqy2);
                unsigned long long dz2 = add2(Z2[j], nqz2);
                unsigned long long d2 = add2(add2(mul2(dx2, dx2), mul2(dy2, dy2)),
                                             mul2(dz2, dz2));
                float dlo, dhi;
                unpack2(d2, dlo, dhi);
                dr[2 * j]     = fminf(dr[2 * j],     dlo);
                dr[2 * j + 1] = fminf(dr[2 * j + 1], dhi);
            }
            float a0 = fmaxf(dr[0], dr[1]);
            float a1 = fmaxf(dr[2], dr[3]);
            float a2 = fmaxf(dr[4], dr[5]);
            float a3 = fmaxf(dr[6], dr[7]);
            float mx = fmaxf(fmaxf(a0, a1), fmaxf(a2, a3));
            wvb = __reduce_max_sync(0xFFFFFFFFu, __float_as_uint(mx));
            // Min original index among bit-equal maxima (this warp).
            unsigned cand = 0xFFFFFFFFu;
            #pragma unroll
            for (int j = 0; j < NPAIR; j++) {
                if (__float_as_uint(dr[2 * j])     == wvb)
                    cand = min(cand, OI2[j] & 0xFFFFu);
                if (__float_as_uint(dr[2 * j + 1]) == wvb)
                    cand = min(cand, OI2[j] >> 16);
            }
            wcand = __reduce_min_sync(0xFFFFFFFFu, cand);
            // Refresh the prune threshold.
            bndf = __fmul_rn(__uint_as_float(wvb), 1.00001f);
        }

        // Single-barrier block argmax over the 32 cached (wvb, wcand) pairs.
        if (lane == 0) pvi[buf * 32 + warp] = make_uint2(wvb, wcand);
        __syncthreads();
        uint2 p2 = pvi[buf * 32 + lane];                 // LDS.64
        unsigned m2 = __reduce_max_sync(0xFFFFFFFFu, p2.x);
        unsigned c2 = (p2.x == m2) ? p2.y : 0xFFFFFFFFu;
        far = __reduce_min_sync(0xFFFFFFFFu, c2);
    }
}

// Gather with channel-tiled blocks (indices preloaded to smem; coalesced
// writes; channel-plane reads get L1/L2 reuse).
#define CT 32            // channels per block
#define MT 512           // samples per block
extern "C" __global__ void __launch_bounds__(256)
gather_kernel(const float* __restrict__ feats,  // [B, C, N]
              float* __restrict__ out_feats)    // [B, M, C]
{
    __shared__ int sn[MT];
    int blk = blockIdx.x;                    // b * 32 + ct * 4 + mt
    int b   = blk >> 5;
    int ct  = (blk >> 2) & 7;                // 8 channel tiles
    int mt  = blk & 3;                       // 4 sample tiles
    int tid = threadIdx.x;

    for (int i = tid; i < MT; i += 256)
        sn[i] = g_idx[b * MM + mt * MT + i];
    __syncthreads();

    int c  = ct * CT + (tid & 31);
    int ml = tid >> 5;                       // 0..7
    const float* fp = feats + ((size_t)b * CC + c) * NN;
    float* op = out_feats + ((size_t)b * MM + mt * MT) * CC + c;

    #pragma unroll 4
    for (int mm = ml; mm < MT; mm += 8)
        op[(size_t)mm * CC] = fp[sn[mm]];
}

// Tiny kernel to keep ncu's "-s 5 -c 1" window on fps_kernel.
extern "C" __global__ void warm_kernel() {}

extern "C" void kernel_launch(void* const* d_in, const int* in_sizes, int n_in,
                              void* d_out, int out_size)
{
    const float* pts   = (const float*)d_in[0];  // [B, 3, N]
    const float* feats = (const float*)d_in[1];  // [B, C, N]
    float* out = (float*)d_out;

    cudaFuncSetAttribute(fps_kernel,
                         cudaFuncAttributeMaxDynamicSharedMemorySize, SMEM_BYTES);

    fps_kernel<<<BB, TT, SMEM_BYTES>>>(pts, out);
    warm_kernel<<<1, 1>>>();
    gather_kernel<<<BB * 32, 256>>>(feats, out + (size_t)BB * MM * 3);
}

// round 15
// speedup vs baseline: 1.1354x; 1.1354x over previous
#include <cuda_runtime.h>

// Problem constants (fixed: B=16, N=8192, C=256, num_points=2048)
#define BB   16
#define NN   8192
#define CC   256
#define MM   2048
#define TT   1024          // threads per FPS block
#define PPT  (NN / TT)     // points per thread = 8
#define NPAIR (PPT / 2)    // f32x2 pairs per thread = 4

// Scratch: selected indices, written by FPS kernel, read by gather kernel.
__device__ int g_idx[BB * MM];

// Dynamic smem: sq4[NN] float4 | pvi[64] uint2 | initv[32] | initi[32] |
//               cent[96] | skx[NN] | ski[NN]
#define SMEM_BYTES (NN * 16 + 64 * 8 + 32 * 4 + 32 * 4 + 96 * 4 + NN * 4 + NN * 4)

// ---- packed f32x2 helpers (sm_103a) ---------------------------------------
__device__ __forceinline__ unsigned long long pack2(float lo, float hi) {
    unsigned long long r;
    asm("mov.b64 %0, {%1, %2};" : "=l"(r) : "f"(lo), "f"(hi));
    return r;
}
__device__ __forceinline__ void unpack2(unsigned long long v, float& lo, float& hi) {
    asm("mov.b64 {%0, %1}, %2;" : "=f"(lo), "=f"(hi) : "l"(v));
}
__device__ __forceinline__ unsigned long long add2(unsigned long long a, unsigned long long b) {
    unsigned long long r;
    asm("add.rn.f32x2 %0, %1, %2;" : "=l"(r) : "l"(a), "l"(b));
    return r;
}
__device__ __forceinline__ unsigned long long mul2(unsigned long long a, unsigned long long b) {
    unsigned long long r;
    asm("mul.rn.f32x2 %0, %1, %2;" : "=l"(r) : "l"(a), "l"(b));
    return r;
}
// ---------------------------------------------------------------------------

__device__ __forceinline__ float warp_sum(float x) {
    #pragma unroll
    for (int o = 16; o > 0; o >>= 1)
        x += __shfl_xor_sync(0xFFFFFFFFu, x, o);
    return x;
}
__device__ __forceinline__ float warp_min(float x) {
    #pragma unroll
    for (int o = 16; o > 0; o >>= 1)
        x = fminf(x, __shfl_xor_sync(0xFFFFFFFFu, x, o));
    return x;
}
__device__ __forceinline__ float warp_max(float x) {
    #pragma unroll
    for (int o = 16; o > 0; o >>= 1)
        x = fmaxf(x, __shfl_xor_sync(0xFFFFFFFFu, x, o));
    return x;
}

extern "C" __global__ void __launch_bounds__(TT, 1)
fps_kernel(const float* __restrict__ pts,   // [B, 3, N]
           float* __restrict__ out_pts)     // [B, M, 3]
{
    extern __shared__ unsigned char smraw[];
    float4*   sq4   = (float4*)smraw;                  // [NN] orig-indexed coords
    uint2*    pvi   = (uint2*)(smraw + NN * 16);       // [64] (val,cand), 2 bufs
    unsigned* initv = (unsigned*)(pvi + 64);           // [32]
    unsigned* initi = initv + 32;                      // [32]
    float*    cent  = (float*)(initi + 32);            // [96]
    float*    skx   = cent + 96;                       // [NN] sort keys (x)
    int*      ski   = (int*)(skx + NN);                // [NN] orig indices

    const int b    = blockIdx.x;
    const int tid  = threadIdx.x;
    const int lane = tid & 31;
    const int warp = tid >> 5;

    const float* px = pts + (size_t)b * 3 * NN;
    const float* py = px + NN;
    const float* pz = px + 2 * NN;

    // ---- load (orig layout), centroid sums, sort-key init ----
    float s1 = 0.f, s2 = 0.f, s3 = 0.f;
    #pragma unroll
    for (int k = 0; k < PPT; k++) {
        int n = tid + k * TT;               // coalesced
        float x = px[n], y = py[n], z = pz[n];
        sq4[n] = make_float4(x, y, z, 0.f);
        skx[n] = x; ski[n] = n;
        s1 += x; s2 += y; s3 += z;
    }

    // Deterministic centroid (exact, one-shot).
    s1 = warp_sum(s1); s2 = warp_sum(s2); s3 = warp_sum(s3);
    if (lane == 0) { cent[warp] = s1; cent[32 + warp] = s2; cent[64 + warp] = s3; }

    // ---- bitonic sort by x (permutation-preserving; quality only affects
    //      pruning, never correctness) ----
    for (int k = 2; k <= NN; k <<= 1) {
        for (int j = k >> 1; j > 0; j >>= 1) {
            __syncthreads();
            #pragma unroll 4
            for (int t = tid; t < NN / 2; t += TT) {
                int i = 2 * t - (t & (j - 1));
                int l = i + j;
                bool up = ((i & k) == 0);
                float a = skx[i], c = skx[l];
                bool sw = up ? (a > c) : (a < c);
                if (sw) {
                    skx[i] = c; skx[l] = a;
                    int ta = ski[i]; ski[i] = ski[l]; ski[l] = ta;
                }
            }
        }
    }
    __syncthreads();

    // ---- reorder into registers: warp w owns sorted ranks [256w, 256w+256) ----
    unsigned long long X2[NPAIR], Y2[NPAIR], Z2[NPAIR];
    unsigned OI2[NPAIR];                    // packed orig indices (lo | hi<<16)
    float dr[PPT];
    float xs[PPT], ys[PPT], zs[PPT];
    unsigned oi[PPT];
    const int base = warp * 256 + lane;
    #pragma unroll
    for (int k = 0; k < PPT; k++) {
        int r = base + 32 * k;
        int idx = ski[r];
        float4 p = sq4[idx];
        xs[k] = p.x; ys[k] = p.y; zs[k] = p.z;
        oi[k] = (unsigned)idx;
        dr[k] = 1e10f;
    }
    #pragma unroll
    for (int j = 0; j < NPAIR; j++) {
        X2[j] = pack2(xs[2 * j], xs[2 * j + 1]);
        Y2[j] = pack2(ys[2 * j], ys[2 * j + 1]);
        Z2[j] = pack2(zs[2 * j], zs[2 * j + 1]);
        OI2[j] = oi[2 * j] | (oi[2 * j + 1] << 16);
    }
    // Warp x-extent (from the points this warp actually holds).
    float xmn = xs[0], xmx = xs[0];
    #pragma unroll
    for (int k = 1; k < PPT; k++) { xmn = fminf(xmn, xs[k]); xmx = fmaxf(xmx, xs[k]); }
    xmn = warp_min(xmn); xmx = warp_max(xmx);

    // Centroid finalize.
    float cx = warp_sum(cent[lane])      * (1.0f / NN);
    float cy = warp_sum(cent[32 + lane]) * (1.0f / NN);
    float cz = warp_sum(cent[64 + lane]) * (1.0f / NN);

    // d0 = ||p - centroid||^2, initial farthest (exact plain form; orig-idx
    // tie-break since held points are no longer index-ordered).
    float best = -1.0f; unsigned bi = 0xFFFFFFFFu;
    #pragma unroll
    for (int k = 0; k < PPT; k++) {
        float dx = xs[k] - cx, dy = ys[k] - cy, dz = zs[k] - cz;
        float d = __fadd_rn(__fadd_rn(__fmul_rn(dx, dx), __fmul_rn(dy, dy)),
                            __fmul_rn(dz, dz));
        if (d > best)            { best = d; bi = oi[k]; }
        else if (d == best && oi[k] < bi) bi = oi[k];
    }
    {
        unsigned vb = __float_as_uint(best);
        unsigned m1 = __reduce_max_sync(0xFFFFFFFFu, vb);
        unsigned c1 = (vb == m1) ? bi : 0xFFFFFFFFu;
        unsigned i1 = __reduce_min_sync(0xFFFFFFFFu, c1);
        if (lane == 0) { initv[warp] = m1; initi[warp] = i1; }
    }
    __syncthreads();
    unsigned far;
    {
        unsigned v2 = initv[lane];
        unsigned i2 = initi[lane];
        unsigned m2 = __reduce_max_sync(0xFFFFFFFFu, v2);
        unsigned c2 = (v2 == m2) ? i2 : 0xFFFFFFFFu;
        far = __reduce_min_sync(0xFFFFFFFFu, c2);
    }

    float* outp = out_pts + (size_t)b * MM * 3;
    int*   idxp = g_idx + b * MM;

    // Per-warp cached state: exact max-dr bits + min orig idx among ties.
    // Valid while the warp skips updates (dr unchanged). First iteration
    // always updates (bnd < 1e10), which initializes wcand properly.
    unsigned wvb   = __float_as_uint(1e10f);
    unsigned wcand = 0xFFFFFFFFu;

    for (int m = 0; m < MM; m++) {
        const int buf = m & 1;
        // Broadcast the selected point (one LDS.128, orig-indexed table).
        float4 q = sq4[far];
        if (tid == 0) {
            idxp[m] = (int)far;
            outp[m * 3 + 0] = q.x;
            outp[m * 3 + 1] = q.y;
            outp[m * 3 + 2] = q.z;
        }

        // Slab prune: if 0.99999*gap_x^2 >= warp max dr, the min-update is a
        // no-op for every point this warp holds -> dr, wvb, wcand all keep
        // their exact values and the warp just joins the reduction.
        float gap = fmaxf(fmaxf(xmn - q.x, q.x - xmx), 0.0f);
        float bnd = __fmul_rn(__fmul_rn(gap, gap), 0.99999f);
        if (bnd < __uint_as_float(wvb)) {
            // Exact update (reference-rounded, no contraction).
            unsigned long long nqx2 = pack2(-q.x, -q.x);
            unsigned long long nqy2 = pack2(-q.y, -q.y);
            unsigned long long nqz2 = pack2(-q.z, -q.z);
            #pragma unroll
            for (int j = 0; j < NPAIR; j++) {
                unsigned long long dx2 = add2(X2[j], nqx2);
                unsigned long long dy2 = add2(Y2[j], nqy2);
                unsigned long long dz2 = add2(Z2[j], nqz2);
                unsigned long long d2 = add2(add2(mul2(dx2, dx2), mul2(dy2, dy2)),
                                             mul2(dz2, dz2));
                float dlo, dhi;
                unpack2(d2, dlo, dhi);
                dr[2 * j]     = fminf(dr[2 * j],     dlo);
                dr[2 * j + 1] = fminf(dr[2 * j + 1], dhi);
            }
            float a0 = fmaxf(dr[0], dr[1]);
            float a1 = fmaxf(dr[2], dr[3]);
            float a2 = fmaxf(dr[4], dr[5]);
            float a3 = fmaxf(dr[6], dr[7]);
            float mx = fmaxf(fmaxf(a0, a1), fmaxf(a2, a3));
            wvb = __reduce_max_sync(0xFFFFFFFFu, __float_as_uint(mx));
            // Min original index among bit-equal maxima (this warp).
            unsigned cand = 0xFFFFFFFFu;
            #pragma unroll
            for (int j = 0; j < NPAIR; j++) {
                if (__float_as_uint(dr[2 * j])     == wvb)
                    cand = min(cand, OI2[j] & 0xFFFFu);
                if (__float_as_uint(dr[2 * j + 1]) == wvb)
                    cand = min(cand, OI2[j] >> 16);
            }
            wcand = __reduce_min_sync(0xFFFFFFFFu, cand);
        }

        // Single-barrier block argmax over the 32 cached (wvb, wcand) pairs.
        if (lane == 0) pvi[buf * 32 + warp] = make_uint2(wvb, wcand);
        __syncthreads();
        uint2 p2 = pvi[buf * 32 + lane];                 // LDS.64
        unsigned m2 = __reduce_max_sync(0xFFFFFFFFu, p2.x);
        unsigned c2 = (p2.x == m2) ? p2.y : 0xFFFFFFFFu;
        far = __reduce_min_sync(0xFFFFFFFFu, c2);
    }
}

// Gather: one block per (batch, 32-channel tile), ALL 2048 samples per block.
// Each 32KB channel plane is touched by exactly ONE block -> unique-sector
// L2 read traffic drops ~2.3x vs the 4-way sample-tiled variant. Writes stay
// 128B-coalesced per (warp, sample).
#define CT 32            // channels per block
extern "C" __global__ void __launch_bounds__(256)
gather_kernel(const float* __restrict__ feats,  // [B, C, N]
              float* __restrict__ out_feats)    // [B, M, C]
{
    __shared__ int sn[MM];
    int blk = blockIdx.x;                    // b * 8 + ct
    int b   = blk >> 3;
    int ct  = blk & 7;                       // 8 channel tiles
    int tid = threadIdx.x;

    for (int i = tid; i < MM; i += 256)
        sn[i] = g_idx[b * MM + i];
    __syncthreads();

    int c  = ct * CT + (tid & 31);
    int ml = tid >> 5;                       // 0..7
    const float* fp = feats + ((size_t)b * CC + c) * NN;
    float* op = out_feats + (size_t)b * MM * CC + c;

    #pragma unroll 8
    for (int mm = ml; mm < MM; mm += 8)
        op[(size_t)mm * CC] = fp[sn[mm]];
}

extern "C" void kernel_launch(void* const* d_in, const int* in_sizes, int n_in,
                              void* d_out, int out_size)
{
    const float* pts   = (const float*)d_in[0];  // [B, 3, N]
    const float* feats = (const float*)d_in[1];  // [B, C, N]
    float* out = (float*)d_out;

    cudaFuncSetAttribute(fps_kernel,
                         cudaFuncAttributeMaxDynamicSharedMemorySize, SMEM_BYTES);

    fps_kernel<<<BB, TT, SMEM_BYTES>>>(pts, out);
    gather_kernel<<<BB * 8, 256>>>(feats, out + (size_t)BB * MM * 3);
}

// round 16
// speedup vs baseline: 1.1584x; 1.0202x over previous
#include <cuda_runtime.h>

// Problem constants (fixed: B=16, N=8192, C=256, num_points=2048)
#define BB   16
#define NN   8192
#define CC   256
#define MM   2048
#define TT   1024          // threads per FPS block
#define PPT  (NN / TT)     // points per thread = 8
#define NPAIR (PPT / 2)    // f32x2 pairs per thread = 4

// Scratch: selected indices, written by FPS kernel, read by gather kernel.
__device__ int g_idx[BB * MM];

// Dynamic smem: sq4[NN] float4 | pvi[64] uint2 | initv[32] | initi[32] |
//               cent[96] | skx[NN] | ski[NN]
#define SMEM_BYTES (NN * 16 + 64 * 8 + 32 * 4 + 32 * 4 + 96 * 4 + NN * 4 + NN * 4)

// ---- packed f32x2 helpers (sm_103a) ---------------------------------------
__device__ __forceinline__ unsigned long long pack2(float lo, float hi) {
    unsigned long long r;
    asm("mov.b64 %0, {%1, %2};" : "=l"(r) : "f"(lo), "f"(hi));
    return r;
}
__device__ __forceinline__ void unpack2(unsigned long long v, float& lo, float& hi) {
    asm("mov.b64 {%0, %1}, %2;" : "=f"(lo), "=f"(hi) : "l"(v));
}
__device__ __forceinline__ unsigned long long add2(unsigned long long a, unsigned long long b) {
    unsigned long long r;
    asm("add.rn.f32x2 %0, %1, %2;" : "=l"(r) : "l"(a), "l"(b));
    return r;
}
__device__ __forceinline__ unsigned long long mul2(unsigned long long a, unsigned long long b) {
    unsigned long long r;
    asm("mul.rn.f32x2 %0, %1, %2;" : "=l"(r) : "l"(a), "l"(b));
    return r;
}
// ---------------------------------------------------------------------------

__device__ __forceinline__ float warp_sum(float x) {
    #pragma unroll
    for (int o = 16; o > 0; o >>= 1)
        x += __shfl_xor_sync(0xFFFFFFFFu, x, o);
    return x;
}
__device__ __forceinline__ float warp_min(float x) {
    #pragma unroll
    for (int o = 16; o > 0; o >>= 1)
        x = fminf(x, __shfl_xor_sync(0xFFFFFFFFu, x, o));
    return x;
}
__device__ __forceinline__ float warp_max(float x) {
    #pragma unroll
    for (int o = 16; o > 0; o >>= 1)
        x = fmaxf(x, __shfl_xor_sync(0xFFFFFFFFu, x, o));
    return x;
}

extern "C" __global__ void __launch_bounds__(TT, 1)
fps_kernel(const float* __restrict__ pts,   // [B, 3, N]
           float* __restrict__ out_pts)     // [B, M, 3]
{
    extern __shared__ unsigned char smraw[];
    float4*   sq4   = (float4*)smraw;                  // [NN] orig-indexed coords
    uint2*    pvi   = (uint2*)(smraw + NN * 16);       // [64] (val,cand), 2 bufs
    unsigned* initv = (unsigned*)(pvi + 64);           // [32]
    unsigned* initi = initv + 32;                      // [32]
    float*    cent  = (float*)(initi + 32);            // [96]
    float*    skx   = cent + 96;                       // [NN] sort keys (x)
    int*      ski   = (int*)(skx + NN);                // [NN] orig indices

    const int b    = blockIdx.x;
    const int tid  = threadIdx.x;
    const int lane = tid & 31;
    const int warp = tid >> 5;

    const float* px = pts + (size_t)b * 3 * NN;
    const float* py = px + NN;
    const float* pz = px + 2 * NN;

    // ---- load (orig layout), centroid sums, sort-key init ----
    float s1 = 0.f, s2 = 0.f, s3 = 0.f;
    #pragma unroll
    for (int k = 0; k < PPT; k++) {
        int n = tid + k * TT;               // coalesced
        float x = px[n], y = py[n], z = pz[n];
        sq4[n] = make_float4(x, y, z, 0.f);
        skx[n] = x; ski[n] = n;
        s1 += x; s2 += y; s3 += z;
    }

    // Deterministic centroid (exact, one-shot).
    s1 = warp_sum(s1); s2 = warp_sum(s2); s3 = warp_sum(s3);
    if (lane == 0) { cent[warp] = s1; cent[32 + warp] = s2; cent[64 + warp] = s3; }

    // ---- bitonic sort by x (permutation-preserving; quality only affects
    //      pruning, never correctness) ----
    for (int k = 2; k <= NN; k <<= 1) {
        for (int j = k >> 1; j > 0; j >>= 1) {
            __syncthreads();
            #pragma unroll 4
            for (int t = tid; t < NN / 2; t += TT) {
                int i = 2 * t - (t & (j - 1));
                int l = i + j;
                bool up = ((i & k) == 0);
                float a = skx[i], c = skx[l];
                bool sw = up ? (a > c) : (a < c);
                if (sw) {
                    skx[i] = c; skx[l] = a;
                    int ta = ski[i]; ski[i] = ski[l]; ski[l] = ta;
                }
            }
        }
    }
    __syncthreads();

    // ---- reorder into registers: warp w owns sorted ranks [256w, 256w+256) ----
    unsigned long long X2[NPAIR], Y2[NPAIR], Z2[NPAIR];
    unsigned OI2[NPAIR];                    // packed orig indices (lo | hi<<16)
    float dr[PPT];
    float xs[PPT], ys[PPT], zs[PPT];
    unsigned oi[PPT];
    const int base = warp * 256 + lane;
    #pragma unroll
    for (int k = 0; k < PPT; k++) {
        int r = base + 32 * k;
        int idx = ski[r];
        float4 p = sq4[idx];
        xs[k] = p.x; ys[k] = p.y; zs[k] = p.z;
        oi[k] = (unsigned)idx;
        dr[k] = 1e10f;
    }
    #pragma unroll
    for (int j = 0; j < NPAIR; j++) {
        X2[j] = pack2(xs[2 * j], xs[2 * j + 1]);
        Y2[j] = pack2(ys[2 * j], ys[2 * j + 1]);
        Z2[j] = pack2(zs[2 * j], zs[2 * j + 1]);
        OI2[j] = oi[2 * j] | (oi[2 * j + 1] << 16);
    }
    // Warp x-extent (from the points this warp actually holds).
    float xmn = xs[0], xmx = xs[0];
    #pragma unroll
    for (int k = 1; k < PPT; k++) { xmn = fminf(xmn, xs[k]); xmx = fmaxf(xmx, xs[k]); }
    xmn = warp_min(xmn); xmx = warp_max(xmx);

    // Centroid finalize.
    float cx = warp_sum(cent[lane])      * (1.0f / NN);
    float cy = warp_sum(cent[32 + lane]) * (1.0f / NN);
    float cz = warp_sum(cent[64 + lane]) * (1.0f / NN);

    // d0 = ||p - centroid||^2, initial farthest (exact plain form; orig-idx
    // tie-break since held points are no longer index-ordered).
    float best = -1.0f; unsigned bi = 0xFFFFFFFFu;
    #pragma unroll
    for (int k = 0; k < PPT; k++) {
        float dx = xs[k] - cx, dy = ys[k] - cy, dz = zs[k] - cz;
        float d = __fadd_rn(__fadd_rn(__fmul_rn(dx, dx), __fmul_rn(dy, dy)),
                            __fmul_rn(dz, dz));
        if (d > best)            { best = d; bi = oi[k]; }
        else if (d == best && oi[k] < bi) bi = oi[k];
    }
    {
        unsigned vb = __float_as_uint(best);
        unsigned m1 = __reduce_max_sync(0xFFFFFFFFu, vb);
        unsigned c1 = (vb == m1) ? bi : 0xFFFFFFFFu;
        unsigned i1 = __reduce_min_sync(0xFFFFFFFFu, c1);
        if (lane == 0) { initv[warp] = m1; initi[warp] = i1; }
    }
    __syncthreads();
    unsigned far;
    {
        unsigned v2 = initv[lane];
        unsigned i2 = initi[lane];
        unsigned m2 = __reduce_max_sync(0xFFFFFFFFu, v2);
        unsigned c2 = (v2 == m2) ? i2 : 0xFFFFFFFFu;
        far = __reduce_min_sync(0xFFFFFFFFu, c2);
    }

    float* outp = out_pts + (size_t)b * MM * 3;
    int*   idxp = g_idx + b * MM;

    // Per-warp cached state: exact max-dr bits + min orig idx among ties.
    // Valid while the warp skips updates (dr unchanged). First iteration
    // always updates (bnd < 1e10), which initializes wcand properly.
    unsigned wvb   = __float_as_uint(1e10f);
    unsigned wcand = 0xFFFFFFFFu;

    for (int m = 0; m < MM; m++) {
        const int buf = m & 1;
        // Broadcast the selected point (one LDS.128, orig-indexed table).
        float4 q = sq4[far];
        if (tid == 0) {
            idxp[m] = (int)far;
            outp[m * 3 + 0] = q.x;
            outp[m * 3 + 1] = q.y;
            outp[m * 3 + 2] = q.z;
        }

        // Slab prune: if 0.99999*gap_x^2 >= warp max dr, the min-update is a
        // no-op for every point this warp holds -> dr, wvb, wcand all keep
        // their exact values and the warp just joins the reduction.
        float gap = fmaxf(fmaxf(xmn - q.x, q.x - xmx), 0.0f);
        float bnd = __fmul_rn(__fmul_rn(gap, gap), 0.99999f);
        if (bnd < __uint_as_float(wvb)) {
            // Exact update (reference-rounded, no contraction).
            unsigned long long nqx2 = pack2(-q.x, -q.x);
            unsigned long long nqy2 = pack2(-q.y, -q.y);
            unsigned long long nqz2 = pack2(-q.z, -q.z);
            #pragma unroll
            for (int j = 0; j < NPAIR; j++) {
                unsigned long long dx2 = add2(X2[j], nqx2);
                unsigned long long dy2 = add2(Y2[j], nqy2);
                unsigned long long dz2 = add2(Z2[j], nqz2);
                unsigned long long d2 = add2(add2(mul2(dx2, dx2), mul2(dy2, dy2)),
                                             mul2(dz2, dz2));
                float dlo, dhi;
                unpack2(d2, dlo, dhi);
                dr[2 * j]     = fminf(dr[2 * j],     dlo);
                dr[2 * j + 1] = fminf(dr[2 * j + 1], dhi);
            }
            float a0 = fmaxf(dr[0], dr[1]);
            float a1 = fmaxf(dr[2], dr[3]);
            float a2 = fmaxf(dr[4], dr[5]);
            float a3 = fmaxf(dr[6], dr[7]);
            float mx = fmaxf(fmaxf(a0, a1), fmaxf(a2, a3));
            wvb = __reduce_max_sync(0xFFFFFFFFu, __float_as_uint(mx));
            // Min original index among bit-equal maxima (this warp).
            unsigned cand = 0xFFFFFFFFu;
            #pragma unroll
            for (int j = 0; j < NPAIR; j++) {
                if (__float_as_uint(dr[2 * j])     == wvb)
                    cand = min(cand, OI2[j] & 0xFFFFu);
                if (__float_as_uint(dr[2 * j + 1]) == wvb)
                    cand = min(cand, OI2[j] >> 16);
            }
            wcand = __reduce_min_sync(0xFFFFFFFFu, cand);
        }

        // Single-barrier block argmax over the 32 cached (wvb, wcand) pairs.
        if (lane == 0) pvi[buf * 32 + warp] = make_uint2(wvb, wcand);
        __syncthreads();
        uint2 p2 = pvi[buf * 32 + lane];                 // LDS.64
        unsigned m2 = __reduce_max_sync(0xFFFFFFFFu, p2.x);
        unsigned c2 = (p2.x == m2) ? p2.y : 0xFFFFFFFFu;
        far = __reduce_min_sync(0xFFFFFFFFu, c2);
    }
}

// Gather: block = (b, 32-channel tile, 512-sample tile) -> 512 blocks (good
// occupancy, round-6 geometry) + batched loads (8 outstanding LDGs before the
// 8 stores) to raise per-thread MLP ~4 -> ~8 and push DRAM toward the roof.
#define CT 32            // channels per block
#define MT 512           // samples per block
extern "C" __global__ void __launch_bounds__(256)
gather_kernel(const float* __restrict__ feats,  // [B, C, N]
              float* __restrict__ out_feats)    // [B, M, C]
{
    __shared__ int sn[MT];
    int blk = blockIdx.x;                    // b * 32 + ct * 4 + mt
    int b   = blk >> 5;
    int ct  = (blk >> 2) & 7;                // 8 channel tiles
    int mt  = blk & 3;                       // 4 sample tiles
    int tid = threadIdx.x;

    for (int i = tid; i < MT; i += 256)
        sn[i] = g_idx[b * MM + mt * MT + i];
    __syncthreads();

    int c  = ct * CT + (tid & 31);
    int ml = tid >> 5;                       // 0..7
    const float* fp = feats + ((size_t)b * CC + c) * NN;
    float* op = out_feats + ((size_t)b * MM + mt * MT) * CC + c;

    // 64 samples per thread (stride 8), in batches of 8 loads then 8 stores.
    #pragma unroll
    for (int i = 0; i < 8; i++) {
        float v[8];
        #pragma unroll
        for (int u = 0; u < 8; u++)
            v[u] = fp[sn[ml + (i * 8 + u) * 8]];
        #pragma unroll
        for (int u = 0; u < 8; u++)
            op[(size_t)(ml + (i * 8 + u) * 8) * CC] = v[u];
    }
}

extern "C" void kernel_launch(void* const* d_in, const int* in_sizes, int n_in,
                              void* d_out, int out_size)
{
    const float* pts   = (const float*)d_in[0];  // [B, 3, N]
    const float* feats = (const float*)d_in[1];  // [B, C, N]
    float* out = (float*)d_out;

    cudaFuncSetAttribute(fps_kernel,
                         cudaFuncAttributeMaxDynamicSharedMemorySize, SMEM_BYTES);

    fps_kernel<<<BB, TT, SMEM_BYTES>>>(pts, out);
    gather_kernel<<<BB * 32, 256>>>(feats, out + (size_t)BB * MM * 3);
}

// round 17
// speedup vs baseline: 1.1744x; 1.0138x over previous
#include <cuda_runtime.h>

// Problem constants (fixed: B=16, N=8192, C=256, num_points=2048)
#define BB   16
#define NN   8192
#define CC   256
#define MM   2048
#define TT   1024          // threads per FPS block
#define PPT  (NN / TT)     // points per thread = 8
#define NPAIR (PPT / 2)    // f32x2 pairs per thread = 4

// Scratch: selected indices, written by FPS kernel, read by gather kernel.
__device__ int g_idx[BB * MM];

// Dynamic smem: sq4[NN] float4 | pvi[64] uint2 | initv[32] | initi[32] |
//               cent[96] | skx[NN] | ski[NN]
#define SMEM_BYTES (NN * 16 + 64 * 8 + 32 * 4 + 32 * 4 + 96 * 4 + NN * 4 + NN * 4)

// ---- packed f32x2 helpers (sm_103a) ---------------------------------------
__device__ __forceinline__ unsigned long long pack2(float lo, float hi) {
    unsigned long long r;
    asm("mov.b64 %0, {%1, %2};" : "=l"(r) : "f"(lo), "f"(hi));
    return r;
}
__device__ __forceinline__ void unpack2(unsigned long long v, float& lo, float& hi) {
    asm("mov.b64 {%0, %1}, %2;" : "=f"(lo), "=f"(hi) : "l"(v));
}
__device__ __forceinline__ unsigned long long add2(unsigned long long a, unsigned long long b) {
    unsigned long long r;
    asm("add.rn.f32x2 %0, %1, %2;" : "=l"(r) : "l"(a), "l"(b));
    return r;
}
__device__ __forceinline__ unsigned long long mul2(unsigned long long a, unsigned long long b) {
    unsigned long long r;
    asm("mul.rn.f32x2 %0, %1, %2;" : "=l"(r) : "l"(a), "l"(b));
    return r;
}
// ---------------------------------------------------------------------------

__device__ __forceinline__ float warp_sum(float x) {
    #pragma unroll
    for (int o = 16; o > 0; o >>= 1)
        x += __shfl_xor_sync(0xFFFFFFFFu, x, o);
    return x;
}
__device__ __forceinline__ float warp_min(float x) {
    #pragma unroll
    for (int o = 16; o > 0; o >>= 1)
        x = fminf(x, __shfl_xor_sync(0xFFFFFFFFu, x, o));
    return x;
}
__device__ __forceinline__ float warp_max(float x) {
    #pragma unroll
    for (int o = 16; o > 0; o >>= 1)
        x = fmaxf(x, __shfl_xor_sync(0xFFFFFFFFu, x, o));
    return x;
}

extern "C" __global__ void __launch_bounds__(TT, 1)
fps_kernel(const float* __restrict__ pts,   // [B, 3, N]
           float* __restrict__ out_pts)     // [B, M, 3]
{
    extern __shared__ unsigned char smraw[];
    float4*   sq4   = (float4*)smraw;                  // [NN] orig-indexed coords
    uint2*    pvi   = (uint2*)(smraw + NN * 16);       // [64] (val,cand), 2 bufs
    unsigned* initv = (unsigned*)(pvi + 64);           // [32]
    unsigned* initi = initv + 32;                      // [32]
    float*    cent  = (float*)(initi + 32);            // [96]
    float*    skx   = cent + 96;                       // [NN] sort keys (x)
    int*      ski   = (int*)(skx + NN);                // [NN] orig indices

    const int b    = blockIdx.x;
    const int tid  = threadIdx.x;
    const int lane = tid & 31;
    const int warp = tid >> 5;

    const float* px = pts + (size_t)b * 3 * NN;
    const float* py = px + NN;
    const float* pz = px + 2 * NN;

    // ---- load (orig layout), centroid sums, sort-key init ----
    float s1 = 0.f, s2 = 0.f, s3 = 0.f;
    #pragma unroll
    for (int k = 0; k < PPT; k++) {
        int n = tid + k * TT;               // coalesced
        float x = px[n], y = py[n], z = pz[n];
        sq4[n] = make_float4(x, y, z, 0.f);
        skx[n] = x; ski[n] = n;
        s1 += x; s2 += y; s3 += z;
    }

    // Deterministic centroid (exact, one-shot).
    s1 = warp_sum(s1); s2 = warp_sum(s2); s3 = warp_sum(s3);
    if (lane == 0) { cent[warp] = s1; cent[32 + warp] = s2; cent[64 + warp] = s3; }

    // ---- bitonic sort by x (permutation-preserving; quality only affects
    //      pruning, never correctness) ----
    for (int k = 2; k <= NN; k <<= 1) {
        for (int j = k >> 1; j > 0; j >>= 1) {
            __syncthreads();
            #pragma unroll 4
            for (int t = tid; t < NN / 2; t += TT) {
                int i = 2 * t - (t & (j - 1));
                int l = i + j;
                bool up = ((i & k) == 0);
                float a = skx[i], c = skx[l];
                bool sw = up ? (a > c) : (a < c);
                if (sw) {
                    skx[i] = c; skx[l] = a;
                    int ta = ski[i]; ski[i] = ski[l]; ski[l] = ta;
                }
            }
        }
    }
    __syncthreads();

    // ---- reorder into registers: warp w owns sorted ranks [256w, 256w+256) ----
    unsigned long long X2[NPAIR], Y2[NPAIR], Z2[NPAIR];
    unsigned OI2[NPAIR];                    // packed orig indices (lo | hi<<16)
    float dr[PPT];
    float xs[PPT], ys[PPT], zs[PPT];
    unsigned oi[PPT];
    const int base = warp * 256 + lane;
    #pragma unroll
    for (int k = 0; k < PPT; k++) {
        int r = base + 32 * k;
        int idx = ski[r];
        float4 p = sq4[idx];
        xs[k] = p.x; ys[k] = p.y; zs[k] = p.z;
        oi[k] = (unsigned)idx;
        dr[k] = 1e10f;
    }
    #pragma unroll
    for (int j = 0; j < NPAIR; j++) {
        X2[j] = pack2(xs[2 * j], xs[2 * j + 1]);
        Y2[j] = pack2(ys[2 * j], ys[2 * j + 1]);
        Z2[j] = pack2(zs[2 * j], zs[2 * j + 1]);
        OI2[j] = oi[2 * j] | (oi[2 * j + 1] << 16);
    }
    // Warp x-extent (from the points this warp actually holds).
    float xmn = xs[0], xmx = xs[0];
    #pragma unroll
    for (int k = 1; k < PPT; k++) { xmn = fminf(xmn, xs[k]); xmx = fmaxf(xmx, xs[k]); }
    xmn = warp_min(xmn); xmx = warp_max(xmx);

    // Centroid finalize.
    float cx = warp_sum(cent[lane])      * (1.0f / NN);
    float cy = warp_sum(cent[32 + lane]) * (1.0f / NN);
    float cz = warp_sum(cent[64 + lane]) * (1.0f / NN);

    // d0 = ||p - centroid||^2, initial farthest (exact plain form; orig-idx
    // tie-break since held points are no longer index-ordered).
    float best = -1.0f; unsigned bi = 0xFFFFFFFFu;
    #pragma unroll
    for (int k = 0; k < PPT; k++) {
        float dx = xs[k] - cx, dy = ys[k] - cy, dz = zs[k] - cz;
        float d = __fadd_rn(__fadd_rn(__fmul_rn(dx, dx), __fmul_rn(dy, dy)),
                            __fmul_rn(dz, dz));
        if (d > best)            { best = d; bi = oi[k]; }
        else if (d == best && oi[k] < bi) bi = oi[k];
    }
    {
        unsigned vb = __float_as_uint(best);
        unsigned m1 = __reduce_max_sync(0xFFFFFFFFu, vb);
        unsigned c1 = (vb == m1) ? bi : 0xFFFFFFFFu;
        unsigned i1 = __reduce_min_sync(0xFFFFFFFFu, c1);
        if (lane == 0) { initv[warp] = m1; initi[warp] = i1; }
    }
    __syncthreads();
    unsigned far;
    {
        unsigned v2 = initv[lane];
        unsigned i2 = initi[lane];
        unsigned m2 = __reduce_max_sync(0xFFFFFFFFu, v2);
        unsigned c2 = (v2 == m2) ? i2 : 0xFFFFFFFFu;
        far = __reduce_min_sync(0xFFFFFFFFu, c2);
    }

    float* outp = out_pts + (size_t)b * MM * 3;
    int*   idxp = g_idx + b * MM;

    // Per-warp cached state: exact max-dr bits + min orig idx among ties.
    // Valid while the warp skips updates (dr unchanged). First iteration
    // always updates (bnd < 1e10), which initializes wcand properly.
    unsigned wvb   = __float_as_uint(1e10f);
    unsigned wcand = 0xFFFFFFFFu;

    for (int m = 0; m < MM; m++) {
        const int buf = m & 1;
        // Broadcast the selected point (one LDS.128, orig-indexed table).
        float4 q = sq4[far];
        if (tid == 0) {
            idxp[m] = (int)far;
            outp[m * 3 + 0] = q.x;
            outp[m * 3 + 1] = q.y;
            outp[m * 3 + 2] = q.z;
        }

        // Slab prune: if 0.99999*gap_x^2 >= warp max dr, the min-update is a
        // no-op for every point this warp holds -> dr, wvb, wcand all keep
        // their exact values and the warp just joins the reduction.
        float gap = fmaxf(fmaxf(xmn - q.x, q.x - xmx), 0.0f);
        float bnd = __fmul_rn(__fmul_rn(gap, gap), 0.99999f);
        if (bnd < __uint_as_float(wvb)) {
            // Exact update (reference-rounded, no contraction).
            unsigned long long nqx2 = pack2(-q.x, -q.x);
            unsigned long long nqy2 = pack2(-q.y, -q.y);
            unsigned long long nqz2 = pack2(-q.z, -q.z);
            #pragma unroll
            for (int j = 0; j < NPAIR; j++) {
                unsigned long long dx2 = add2(X2[j], nqx2);
                unsigned long long dy2 = add2(Y2[j], nqy2);
                unsigned long long dz2 = add2(Z2[j], nqz2);
                unsigned long long d2 = add2(add2(mul2(dx2, dx2), mul2(dy2, dy2)),
                                             mul2(dz2, dz2));
                float dlo, dhi;
                unpack2(d2, dlo, dhi);
                dr[2 * j]     = fminf(dr[2 * j],     dlo);
                dr[2 * j + 1] = fminf(dr[2 * j + 1], dhi);
            }
            float a0 = fmaxf(dr[0], dr[1]);
            float a1 = fmaxf(dr[2], dr[3]);
            float a2 = fmaxf(dr[4], dr[5]);
            float a3 = fmaxf(dr[6], dr[7]);
            float mx = fmaxf(fmaxf(a0, a1), fmaxf(a2, a3));
            wvb = __reduce_max_sync(0xFFFFFFFFu, __float_as_uint(mx));
            // Min original index among bit-equal maxima (this warp).
            unsigned cand = 0xFFFFFFFFu;
            #pragma unroll
            for (int j = 0; j < NPAIR; j++) {
                if (__float_as_uint(dr[2 * j])     == wvb)
                    cand = min(cand, OI2[j] & 0xFFFFu);
                if (__float_as_uint(dr[2 * j + 1]) == wvb)
                    cand = min(cand, OI2[j] >> 16);
            }
            wcand = __reduce_min_sync(0xFFFFFFFFu, cand);
        }

        // Single-barrier block argmax over the 32 cached (wvb, wcand) pairs.
        if (lane == 0) pvi[buf * 32 + warp] = make_uint2(wvb, wcand);
        __syncthreads();
        uint2 p2 = pvi[buf * 32 + lane];                 // LDS.64
        unsigned m2 = __reduce_max_sync(0xFFFFFFFFu, p2.x);
        unsigned c2 = (p2.x == m2) ? p2.y : 0xFFFFFFFFu;
        far = __reduce_min_sync(0xFFFFFFFFu, c2);
    }
}

// Gather: block = (b, 32-channel tile, 256-sample tile) -> 1024 blocks
// (~7 blocks/SM -> occupancy ~70%) + batched loads (8 outstanding LDGs before
// the 8 stores) so chip-level MLP pushes DRAM toward the roof.
#define CT 32            // channels per block
#define MT 256           // samples per block
extern "C" __global__ void __launch_bounds__(256)
gather_kernel(const float* __restrict__ feats,  // [B, C, N]
              float* __restrict__ out_feats)    // [B, M, C]
{
    __shared__ int sn[MT];
    int blk = blockIdx.x;                    // b * 64 + ct * 8 + mt
    int b   = blk >> 6;
    int ct  = (blk >> 3) & 7;                // 8 channel tiles
    int mt  = blk & 7;                       // 8 sample tiles
    int tid = threadIdx.x;

    if (tid < MT)
        sn[tid] = g_idx[b * MM + mt * MT + tid];
    __syncthreads();

    int c  = ct * CT + (tid & 31);
    int ml = tid >> 5;                       // 0..7
    const float* fp = feats + ((size_t)b * CC + c) * NN;
    float* op = out_feats + ((size_t)b * MM + mt * MT) * CC + c;

    // 32 samples per thread (stride 8), in batches of 8 loads then 8 stores.
    #pragma unroll
    for (int i = 0; i < 4; i++) {
        float v[8];
        #pragma unroll
        for (int u = 0; u < 8; u++)
            v[u] = fp[sn[ml + (i * 8 + u) * 8]];
        #pragma unroll
        for (int u = 0; u < 8; u++)
            op[(size_t)(ml + (i * 8 + u) * 8) * CC] = v[u];
    }
}

extern "C" void kernel_launch(void* const* d_in, const int* in_sizes, int n_in,
                              void* d_out, int out_size)
{
    const float* pts   = (const float*)d_in[0];  // [B, 3, N]
    const float* feats = (const float*)d_in[1];  // [B, C, N]
    float* out = (float*)d_out;

    cudaFuncSetAttribute(fps_kernel,
                         cudaFuncAttributeMaxDynamicSharedMemorySize, SMEM_BYTES);

    fps_kernel<<<BB, TT, SMEM_BYTES>>>(pts, out);
    gather_kernel<<<BB * 64, 256>>>(feats, out + (size_t)BB * MM * 3);
}